// round 12
// baseline (speedup 1.0000x reference)
#include <cuda_runtime.h>
#include <stdint.h>

// Problem constants (fixed shapes from reference: B=8, K=4, N=131072)
#define T_TOTAL   4194304      // B*K*N
#define TILE      4096         // expansion-kernel tile (8 warps x 512)
#define NBLK      1024         // T_TOTAL / TILE
#define TILE_P    8192         // pack-kernel tile (2 chunks of 4096)
#define NBLK_P    512
#define NT        256          // threads per block
#define NWARP     (T_TOTAL / 512)   // 8192 warp-chunks of 512 elems
#define NEG_IDLE_F (-100000000.0f)
#define NEG_FILL_F (-1000.0f)

// Scratch (device globals — no allocation allowed in kernel_launch)
__device__ unsigned g_wsum[NWARP];            // packed per-warp-chunk sums (s | a<<16)
__device__ int      g_woff_s[NWARP];          // per-warp-chunk global exclusive offsets
__device__ int      g_woff_a[NWARP];
__device__ unsigned g_packed[T_TOTAL / 16];   // 1MB: 16 surf bits | 16 air bits

// ---------------------------------------------------------------------------
// Kernel 1: read both masks once, bit-pack to 1MB scratch, per-warp-chunk sums.
// v2: each thread handles TWO independent 16-elem chunks (16 uint4 loads in
// flight) for higher MLP. No smem, no barriers.
// ---------------------------------------------------------------------------
__global__ __launch_bounds__(NT) void k_pack(const uint32_t* __restrict__ ms,
                                             const uint32_t* __restrict__ ma) {
    int blk = blockIdx.x, tid = threadIdx.x;
    int lane = tid & 31, w = tid >> 5;
    size_t eA = (size_t)blk * TILE_P + (size_t)tid * 16;
    size_t eB = eA + 4096;
    const uint4* sA = reinterpret_cast<const uint4*>(ms + eA);
    const uint4* aA = reinterpret_cast<const uint4*>(ma + eA);
    const uint4* sB = reinterpret_cast<const uint4*>(ms + eB);
    const uint4* aB = reinterpret_cast<const uint4*>(ma + eB);

    unsigned bsA = 0, baA = 0, bsB = 0, baB = 0;
    #pragma unroll
    for (int i = 0; i < 4; i++) {
        uint4 s0 = sA[i], a0 = aA[i], s1 = sB[i], a1 = aB[i];
        bsA |= ((s0.x != 0u) << (i * 4)) | ((s0.y != 0u) << (i * 4 + 1)) |
               ((s0.z != 0u) << (i * 4 + 2)) | ((s0.w != 0u) << (i * 4 + 3));
        baA |= ((a0.x != 0u) << (i * 4)) | ((a0.y != 0u) << (i * 4 + 1)) |
               ((a0.z != 0u) << (i * 4 + 2)) | ((a0.w != 0u) << (i * 4 + 3));
        bsB |= ((s1.x != 0u) << (i * 4)) | ((s1.y != 0u) << (i * 4 + 1)) |
               ((s1.z != 0u) << (i * 4 + 2)) | ((s1.w != 0u) << (i * 4 + 3));
        baB |= ((a1.x != 0u) << (i * 4)) | ((a1.y != 0u) << (i * 4 + 1)) |
               ((a1.z != 0u) << (i * 4 + 2)) | ((a1.w != 0u) << (i * 4 + 3));
    }
    g_packed[blk * 512 + tid]       = bsA | (baA << 16);
    g_packed[blk * 512 + 256 + tid] = bsB | (baB << 16);

    int pA = __popc(bsA) | (__popc(baA) << 16);
    int pB = __popc(bsB) | (__popc(baB) << 16);
    #pragma unroll
    for (int o = 16; o > 0; o >>= 1) {
        pA += __shfl_xor_sync(0xffffffffu, pA, o);
        pB += __shfl_xor_sync(0xffffffffu, pB, o);
    }
    if (lane == 0) {
        g_wsum[blk * 16 + w]     = (unsigned)pA;   // chunk A = warp-chunks 0..7
        g_wsum[blk * 16 + 8 + w] = (unsigned)pB;   // chunk B = warp-chunks 8..15
    }
}

// ---------------------------------------------------------------------------
// Kernel 2: exclusive scan of 8192 packed warp sums -> per-warp-chunk offsets.
// One block, 1024 threads, 8 entries each.
// ---------------------------------------------------------------------------
__global__ __launch_bounds__(1024) void k_scan() {
    int tid = threadIdx.x, lane = tid & 31, w = tid >> 5;
    int ls[8], la_[8];
    int ss = 0, sa = 0;
    #pragma unroll
    for (int i = 0; i < 8; i++) {
        unsigned pw = g_wsum[tid * 8 + i];
        ls[i] = ss; la_[i] = sa;
        ss += (int)(pw & 0xffffu);
        sa += (int)(pw >> 16);
    }
    int is = ss, ia = sa;
    #pragma unroll
    for (int o = 1; o < 32; o <<= 1) {
        int t = __shfl_up_sync(0xffffffffu, is, o); if (lane >= o) is += t;
        t     = __shfl_up_sync(0xffffffffu, ia, o); if (lane >= o) ia += t;
    }
    __shared__ int ws[32], wa[32];
    if (lane == 31) { ws[w] = is; wa[w] = ia; }
    __syncthreads();
    if (w == 0) {
        int ts = ws[lane], ta = wa[lane];
        int js = ts, ja = ta;
        #pragma unroll
        for (int o = 1; o < 32; o <<= 1) {
            int t = __shfl_up_sync(0xffffffffu, js, o); if (lane >= o) js += t;
            t     = __shfl_up_sync(0xffffffffu, ja, o); if (lane >= o) ja += t;
        }
        ws[lane] = js - ts;
        wa[lane] = ja - ta;
    }
    __syncthreads();
    int base_s = ws[w] + is - ss;
    int base_a = wa[w] + ia - sa;
    #pragma unroll
    for (int i = 0; i < 8; i++) {
        g_woff_s[tid * 8 + i] = base_s + ls[i];
        g_woff_a[tid * 8 + i] = base_a + la_[i];
    }
}

// ---------------------------------------------------------------------------
// Kernel 3a: logits surface+air expansion. Warp-autonomous, barrier-free.
// Light kernel: 2 gathers + 2 coalesced float4 stores per lane-iter.
// ---------------------------------------------------------------------------
__global__ __launch_bounds__(NT) void k_lsla(
    const float* __restrict__ ls, const float* __restrict__ la,
    const float* __restrict__ idle_st,
    float* __restrict__ ls_out, float* __restrict__ la_out) {

    int blk = blockIdx.x, tid = threadIdx.x;
    int lane = tid & 31, w = tid >> 5;
    int gw = blk * 8 + w;

    unsigned wbits = g_packed[gw * 32 + lane];

    float idle   = idle_st[blk >> 5];
    float scale  = 1.0f - idle;
    float negadd = idle * NEG_IDLE_F;

    unsigned ms4[4], ma4[4];
    unsigned shift = (lane & 3) * 4;
    unsigned cnt_s = 0, cnt_a = 0;
    #pragma unroll
    for (int j = 0; j < 4; j++) {
        unsigned word = __shfl_sync(0xffffffffu, wbits, j * 8 + (lane >> 2));
        ms4[j] = (word >> shift) & 0xFu;
        ma4[j] = (word >> (16 + shift)) & 0xFu;
        cnt_s |= __popc(ms4[j]) << (j * 8);
        cnt_a |= __popc(ma4[j]) << (j * 8);
    }
    unsigned ip_s = cnt_s, ip_a = cnt_a;
    #pragma unroll
    for (int o = 1; o < 32; o <<= 1) {
        unsigned ts = __shfl_up_sync(0xffffffffu, ip_s, o);
        unsigned ta = __shfl_up_sync(0xffffffffu, ip_a, o);
        if (lane >= o) { ip_s += ts; ip_a += ta; }
    }
    unsigned tot_s = __shfl_sync(0xffffffffu, ip_s, 31);
    unsigned tot_a = __shfl_sync(0xffffffffu, ip_a, 31);
    unsigned ep_s = ip_s - cnt_s;
    unsigned ep_a = ip_a - cnt_a;

    int run_s = g_woff_s[gw];
    int run_a = g_woff_a[gw];
    size_t wbase = (size_t)blk * TILE + (size_t)w * 512;

    #pragma unroll
    for (int j = 0; j < 4; j++) {
        size_t e0 = wbase + j * 128 + lane * 4;
        int base_s = run_s + (int)((ep_s >> (j * 8)) & 0xffu);
        int base_a = run_a + (int)((ep_a >> (j * 8)) & 0xffu);
        run_s += (int)((tot_s >> (j * 8)) & 0xffu);
        run_a += (int)((tot_a >> (j * 8)) & 0xffu);
        unsigned mS = ms4[j], mA = ma4[j];

        float os[4], oa[4];
        #pragma unroll
        for (int q = 0; q < 4; q++) {
            if ((mS >> q) & 1u) {
                int idx = base_s + __popc(mS & ((1u << q) - 1u));
                os[q] = __ldg(ls + idx) * scale + negadd;
            } else os[q] = NEG_FILL_F;
            if ((mA >> q) & 1u) {
                int idx = base_a + __popc(mA & ((1u << q) - 1u));
                oa[q] = __ldg(la + idx) * scale + negadd;
            } else oa[q] = NEG_FILL_F;
        }
        *reinterpret_cast<float4*>(ls_out + e0) = make_float4(os[0], os[1], os[2], os[3]);
        *reinterpret_cast<float4*>(la_out + e0) = make_float4(oa[0], oa[1], oa[2], oa[3]);
    }
}

// ---------------------------------------------------------------------------
// Kernel 3b: rgb expansion. Warp-autonomous, barrier-free, surface mask only.
// 3 gathers + 3 float4 stores per lane-iter.
// ---------------------------------------------------------------------------
__global__ __launch_bounds__(NT) void k_rgb(
    const float* __restrict__ rgb, const float* __restrict__ idle_st,
    float* __restrict__ rgb_out) {

    int blk = blockIdx.x, tid = threadIdx.x;
    int lane = tid & 31, w = tid >> 5;
    int gw = blk * 8 + w;

    unsigned wbits = g_packed[gw * 32 + lane];

    float scale = 1.0f - idle_st[blk >> 5];

    unsigned ms4[4];
    unsigned shift = (lane & 3) * 4;
    unsigned cnt_s = 0;
    #pragma unroll
    for (int j = 0; j < 4; j++) {
        unsigned word = __shfl_sync(0xffffffffu, wbits, j * 8 + (lane >> 2));
        ms4[j] = (word >> shift) & 0xFu;
        cnt_s |= __popc(ms4[j]) << (j * 8);
    }
    unsigned ip_s = cnt_s;
    #pragma unroll
    for (int o = 1; o < 32; o <<= 1) {
        unsigned ts = __shfl_up_sync(0xffffffffu, ip_s, o);
        if (lane >= o) ip_s += ts;
    }
    unsigned tot_s = __shfl_sync(0xffffffffu, ip_s, 31);
    unsigned ep_s = ip_s - cnt_s;

    int run_s = g_woff_s[gw];
    size_t wbase = (size_t)blk * TILE + (size_t)w * 512;

    #pragma unroll
    for (int j = 0; j < 4; j++) {
        size_t e0 = wbase + j * 128 + lane * 4;
        int base_s = run_s + (int)((ep_s >> (j * 8)) & 0xffu);
        run_s += (int)((tot_s >> (j * 8)) & 0xffu);
        unsigned mS = ms4[j];

        float ro[12];
        #pragma unroll
        for (int q = 0; q < 4; q++) {
            if ((mS >> q) & 1u) {
                int idx = base_s + __popc(mS & ((1u << q) - 1u));
                const float* rp = rgb + (size_t)idx * 3;
                ro[q * 3 + 0] = rp[0] * scale;
                ro[q * 3 + 1] = rp[1] * scale;
                ro[q * 3 + 2] = rp[2] * scale;
            } else {
                ro[q * 3 + 0] = 0.0f; ro[q * 3 + 1] = 0.0f; ro[q * 3 + 2] = 0.0f;
            }
        }
        float4* rout = reinterpret_cast<float4*>(rgb_out + e0 * 3);
        rout[0] = make_float4(ro[0], ro[1],  ro[2],  ro[3]);
        rout[1] = make_float4(ro[4], ro[5],  ro[6],  ro[7]);
        rout[2] = make_float4(ro[8], ro[9],  ro[10], ro[11]);
    }
}

// ---------------------------------------------------------------------------
// Launch: 4 kernels (pack, scan, rgb, lsla). Graph-capturable.
// ---------------------------------------------------------------------------
extern "C" void kernel_launch(void* const* d_in, const int* in_sizes, int n_in,
                              void* d_out, int out_size) {
    const float*    rgb  = (const float*)d_in[0];
    const float*    ls   = (const float*)d_in[1];
    const float*    la   = (const float*)d_in[2];
    const uint32_t* msf  = (const uint32_t*)d_in[3];
    const uint32_t* maf  = (const uint32_t*)d_in[4];
    const float*    idle = (const float*)d_in[5];

    float* out     = (float*)d_out;
    float* rgb_out = out;
    float* ls_out  = out + (size_t)T_TOTAL * 3;
    float* la_out  = ls_out + T_TOTAL;

    k_pack<<<NBLK_P, NT>>>(msf, maf);
    k_scan<<<1, 1024>>>();
    k_rgb<<<NBLK, NT>>>(rgb, idle, rgb_out);
    k_lsla<<<NBLK, NT>>>(ls, la, idle, ls_out, la_out);
}

// round 14
// speedup vs baseline: 1.1026x; 1.1026x over previous
#include <cuda_runtime.h>
#include <stdint.h>

// Problem constants (fixed shapes from reference: B=8, K=4, N=131072)
#define T_TOTAL   4194304      // B*K*N
#define TILE      4096         // expansion tile (8 warps x 512)
#define NBLK      1024         // T_TOTAL / TILE
#define TILE_P    8192         // pack-kernel tile (2 chunks of 4096)
#define NBLK_P    512
#define NT        256          // threads per block
#define NWARP     (T_TOTAL / 512)   // 8192 warp-chunks of 512 elems
#define NEG_IDLE_F (-100000000.0f)
#define NEG_FILL_F (-1000.0f)

// Scratch (device globals — no allocation allowed in kernel_launch)
__device__ unsigned g_wsum[NWARP];            // packed per-warp-chunk sums (s | a<<16)
__device__ int      g_woff_s[NWARP];          // per-warp-chunk global exclusive offsets
__device__ int      g_woff_a[NWARP];
__device__ unsigned g_packed[T_TOTAL / 16];   // 1MB: 16 surf bits | 16 air bits

__device__ __forceinline__ void stcs4(float* p, float4 v) {
    // Streaming store: outputs are write-once -> evict-first, keep L2 for inputs.
    asm volatile("st.global.cs.v4.f32 [%0], {%1,%2,%3,%4};"
                 :: "l"(p), "f"(v.x), "f"(v.y), "f"(v.z), "f"(v.w) : "memory");
}

// ---------------------------------------------------------------------------
// Kernel 1: read both masks once, bit-pack to 1MB scratch, per-warp-chunk sums.
// Each thread handles TWO independent 16-elem chunks (16 uint4 loads in
// flight). No smem, no barriers.
// ---------------------------------------------------------------------------
__global__ __launch_bounds__(NT) void k_pack(const uint32_t* __restrict__ ms,
                                             const uint32_t* __restrict__ ma) {
    int blk = blockIdx.x, tid = threadIdx.x;
    int lane = tid & 31, w = tid >> 5;
    size_t eA = (size_t)blk * TILE_P + (size_t)tid * 16;
    size_t eB = eA + 4096;
    const uint4* sA = reinterpret_cast<const uint4*>(ms + eA);
    const uint4* aA = reinterpret_cast<const uint4*>(ma + eA);
    const uint4* sB = reinterpret_cast<const uint4*>(ms + eB);
    const uint4* aB = reinterpret_cast<const uint4*>(ma + eB);

    unsigned bsA = 0, baA = 0, bsB = 0, baB = 0;
    #pragma unroll
    for (int i = 0; i < 4; i++) {
        uint4 s0 = sA[i], a0 = aA[i], s1 = sB[i], a1 = aB[i];
        bsA |= ((s0.x != 0u) << (i * 4)) | ((s0.y != 0u) << (i * 4 + 1)) |
               ((s0.z != 0u) << (i * 4 + 2)) | ((s0.w != 0u) << (i * 4 + 3));
        baA |= ((a0.x != 0u) << (i * 4)) | ((a0.y != 0u) << (i * 4 + 1)) |
               ((a0.z != 0u) << (i * 4 + 2)) | ((a0.w != 0u) << (i * 4 + 3));
        bsB |= ((s1.x != 0u) << (i * 4)) | ((s1.y != 0u) << (i * 4 + 1)) |
               ((s1.z != 0u) << (i * 4 + 2)) | ((s1.w != 0u) << (i * 4 + 3));
        baB |= ((a1.x != 0u) << (i * 4)) | ((a1.y != 0u) << (i * 4 + 1)) |
               ((a1.z != 0u) << (i * 4 + 2)) | ((a1.w != 0u) << (i * 4 + 3));
    }
    g_packed[blk * 512 + tid]       = bsA | (baA << 16);
    g_packed[blk * 512 + 256 + tid] = bsB | (baB << 16);

    int pA = __popc(bsA) | (__popc(baA) << 16);
    int pB = __popc(bsB) | (__popc(baB) << 16);
    #pragma unroll
    for (int o = 16; o > 0; o >>= 1) {
        pA += __shfl_xor_sync(0xffffffffu, pA, o);
        pB += __shfl_xor_sync(0xffffffffu, pB, o);
    }
    if (lane == 0) {
        g_wsum[blk * 16 + w]     = (unsigned)pA;
        g_wsum[blk * 16 + 8 + w] = (unsigned)pB;
    }
}

// ---------------------------------------------------------------------------
// Kernel 2: exclusive scan of 8192 packed warp sums -> per-warp-chunk offsets.
// ---------------------------------------------------------------------------
__global__ __launch_bounds__(1024) void k_scan() {
    int tid = threadIdx.x, lane = tid & 31, w = tid >> 5;
    int ls[8], la_[8];
    int ss = 0, sa = 0;
    #pragma unroll
    for (int i = 0; i < 8; i++) {
        unsigned pw = g_wsum[tid * 8 + i];
        ls[i] = ss; la_[i] = sa;
        ss += (int)(pw & 0xffffu);
        sa += (int)(pw >> 16);
    }
    int is = ss, ia = sa;
    #pragma unroll
    for (int o = 1; o < 32; o <<= 1) {
        int t = __shfl_up_sync(0xffffffffu, is, o); if (lane >= o) is += t;
        t     = __shfl_up_sync(0xffffffffu, ia, o); if (lane >= o) ia += t;
    }
    __shared__ int ws[32], wa[32];
    if (lane == 31) { ws[w] = is; wa[w] = ia; }
    __syncthreads();
    if (w == 0) {
        int ts = ws[lane], ta = wa[lane];
        int js = ts, ja = ta;
        #pragma unroll
        for (int o = 1; o < 32; o <<= 1) {
            int t = __shfl_up_sync(0xffffffffu, js, o); if (lane >= o) js += t;
            t     = __shfl_up_sync(0xffffffffu, ja, o); if (lane >= o) ja += t;
        }
        ws[lane] = js - ts;
        wa[lane] = ja - ta;
    }
    __syncthreads();
    int base_s = ws[w] + is - ss;
    int base_a = wa[w] + ia - sa;
    #pragma unroll
    for (int i = 0; i < 8; i++) {
        g_woff_s[tid * 8 + i] = base_s + ls[i];
        g_woff_a[tid * 8 + i] = base_a + la_[i];
    }
}

// ---------------------------------------------------------------------------
// Kernel 3: heterogeneous expansion — 2048 blocks, role = blockIdx.x & 1.
// Even blocks: rgb gather+store. Odd blocks: ls+la gathers+stores.
// Adjacent blocks alternate roles -> every SM runs a mix concurrently.
// Warp-autonomous, barrier-free, forced 8 blocks/SM for high occupancy.
// ---------------------------------------------------------------------------
__global__ __launch_bounds__(NT, 8) void k_expand(
    const float* __restrict__ rgb, const float* __restrict__ ls,
    const float* __restrict__ la,  const float* __restrict__ idle_st,
    float* __restrict__ rgb_out, float* __restrict__ ls_out,
    float* __restrict__ la_out) {

    int bid = blockIdx.x;
    int blk = bid >> 1;          // tile 0..1023
    int role = bid & 1;
    int tid = threadIdx.x;
    int lane = tid & 31, w = tid >> 5;
    int gw = blk * 8 + w;

    unsigned wbits = g_packed[gw * 32 + lane];
    float idle  = idle_st[blk >> 5];
    float scale = 1.0f - idle;

    unsigned shift = (lane & 3) * 4;
    size_t wbase = (size_t)blk * TILE + (size_t)w * 512;

    if (role == 0) {
        // ---- RGB path (surface mask only) ----
        unsigned ms4[4];
        unsigned cnt_s = 0;
        #pragma unroll
        for (int j = 0; j < 4; j++) {
            unsigned word = __shfl_sync(0xffffffffu, wbits, j * 8 + (lane >> 2));
            ms4[j] = (word >> shift) & 0xFu;
            cnt_s |= __popc(ms4[j]) << (j * 8);
        }
        unsigned ip_s = cnt_s;
        #pragma unroll
        for (int o = 1; o < 32; o <<= 1) {
            unsigned ts = __shfl_up_sync(0xffffffffu, ip_s, o);
            if (lane >= o) ip_s += ts;
        }
        unsigned tot_s = __shfl_sync(0xffffffffu, ip_s, 31);
        unsigned ep_s = ip_s - cnt_s;
        int run_s = g_woff_s[gw];

        #pragma unroll
        for (int j = 0; j < 4; j++) {
            size_t e0 = wbase + j * 128 + lane * 4;
            int base_s = run_s + (int)((ep_s >> (j * 8)) & 0xffu);
            run_s += (int)((tot_s >> (j * 8)) & 0xffu);
            unsigned mS = ms4[j];

            float ro[12];
            #pragma unroll
            for (int q = 0; q < 4; q++) {
                if ((mS >> q) & 1u) {
                    int idx = base_s + __popc(mS & ((1u << q) - 1u));
                    const float* rp = rgb + (size_t)idx * 3;
                    ro[q * 3 + 0] = __ldg(rp + 0) * scale;
                    ro[q * 3 + 1] = __ldg(rp + 1) * scale;
                    ro[q * 3 + 2] = __ldg(rp + 2) * scale;
                } else {
                    ro[q * 3 + 0] = 0.0f; ro[q * 3 + 1] = 0.0f; ro[q * 3 + 2] = 0.0f;
                }
            }
            float* rout = rgb_out + e0 * 3;
            stcs4(rout + 0, make_float4(ro[0], ro[1],  ro[2],  ro[3]));
            stcs4(rout + 4, make_float4(ro[4], ro[5],  ro[6],  ro[7]));
            stcs4(rout + 8, make_float4(ro[8], ro[9],  ro[10], ro[11]));
        }
    } else {
        // ---- Logits path (both masks) ----
        float negadd = idle * NEG_IDLE_F;
        unsigned ms4[4], ma4[4];
        unsigned cnt_s = 0, cnt_a = 0;
        #pragma unroll
        for (int j = 0; j < 4; j++) {
            unsigned word = __shfl_sync(0xffffffffu, wbits, j * 8 + (lane >> 2));
            ms4[j] = (word >> shift) & 0xFu;
            ma4[j] = (word >> (16 + shift)) & 0xFu;
            cnt_s |= __popc(ms4[j]) << (j * 8);
            cnt_a |= __popc(ma4[j]) << (j * 8);
        }
        unsigned ip_s = cnt_s, ip_a = cnt_a;
        #pragma unroll
        for (int o = 1; o < 32; o <<= 1) {
            unsigned ts = __shfl_up_sync(0xffffffffu, ip_s, o);
            unsigned ta = __shfl_up_sync(0xffffffffu, ip_a, o);
            if (lane >= o) { ip_s += ts; ip_a += ta; }
        }
        unsigned tot_s = __shfl_sync(0xffffffffu, ip_s, 31);
        unsigned tot_a = __shfl_sync(0xffffffffu, ip_a, 31);
        unsigned ep_s = ip_s - cnt_s;
        unsigned ep_a = ip_a - cnt_a;
        int run_s = g_woff_s[gw];
        int run_a = g_woff_a[gw];

        #pragma unroll
        for (int j = 0; j < 4; j++) {
            size_t e0 = wbase + j * 128 + lane * 4;
            int base_s = run_s + (int)((ep_s >> (j * 8)) & 0xffu);
            int base_a = run_a + (int)((ep_a >> (j * 8)) & 0xffu);
            run_s += (int)((tot_s >> (j * 8)) & 0xffu);
            run_a += (int)((tot_a >> (j * 8)) & 0xffu);
            unsigned mS = ms4[j], mA = ma4[j];

            float os[4], oa[4];
            #pragma unroll
            for (int q = 0; q < 4; q++) {
                if ((mS >> q) & 1u) {
                    int idx = base_s + __popc(mS & ((1u << q) - 1u));
                    os[q] = __ldg(ls + idx) * scale + negadd;
                } else os[q] = NEG_FILL_F;
                if ((mA >> q) & 1u) {
                    int idx = base_a + __popc(mA & ((1u << q) - 1u));
                    oa[q] = __ldg(la + idx) * scale + negadd;
                } else oa[q] = NEG_FILL_F;
            }
            stcs4(ls_out + e0, make_float4(os[0], os[1], os[2], os[3]));
            stcs4(la_out + e0, make_float4(oa[0], oa[1], oa[2], oa[3]));
        }
    }
}

// ---------------------------------------------------------------------------
// Launch: 3 kernels (pack, scan, heterogeneous expand). Graph-capturable.
// ---------------------------------------------------------------------------
extern "C" void kernel_launch(void* const* d_in, const int* in_sizes, int n_in,
                              void* d_out, int out_size) {
    const float*    rgb  = (const float*)d_in[0];
    const float*    ls   = (const float*)d_in[1];
    const float*    la   = (const float*)d_in[2];
    const uint32_t* msf  = (const uint32_t*)d_in[3];
    const uint32_t* maf  = (const uint32_t*)d_in[4];
    const float*    idle = (const float*)d_in[5];

    float* out     = (float*)d_out;
    float* rgb_out = out;
    float* ls_out  = out + (size_t)T_TOTAL * 3;
    float* la_out  = ls_out + T_TOTAL;

    k_pack<<<NBLK_P, NT>>>(msf, maf);
    k_scan<<<1, 1024>>>();
    k_expand<<<NBLK * 2, NT>>>(rgb, ls, la, idle, rgb_out, ls_out, la_out);
}